// round 15
// baseline (speedup 1.0000x reference)
#include <cuda_runtime.h>
#include <cuda_fp16.h>
#include <cstdint>
#include <cstddef>

#define D_HID 2048
#define T_LEN 4096
#define M_ROWS 8192
#define KW 8192

// ---------------- scratch (static device arrays: allocation-guard safe) ----
__device__ __align__(256) __half g_xh[(size_t)M_ROWS * D_HID];
__device__ __align__(256) __half g_w1h[(size_t)D_HID * D_HID];
__device__ __align__(256) __half g_w2h[(size_t)KW * D_HID];
__device__ __align__(256) __half g_hh[(size_t)M_ROWS * D_HID];

// ---------------- helpers ---------------------------------------------------
__device__ __forceinline__ uint32_t smem_u32(const void* p) {
    uint32_t a;
    asm("{ .reg .u64 t; cvta.to.shared.u64 t, %1; cvt.u32.u64 %0, t; }"
        : "=r"(a) : "l"(p));
    return a;
}
__device__ __forceinline__ void cp16(uint32_t dst, const void* src) {
    asm volatile("cp.async.cg.shared.global [%0], [%1], 16;" :: "r"(dst), "l"(src));
}
#define CP_COMMIT() asm volatile("cp.async.commit_group;" ::: "memory")
#define CP_WAIT1()  asm volatile("cp.async.wait_group 1;" ::: "memory")

__device__ __forceinline__ void ldsm4(uint32_t r[4], uint32_t addr) {
    asm volatile("ldmatrix.sync.aligned.m8n8.x4.shared.b16 {%0,%1,%2,%3}, [%4];"
        : "=r"(r[0]), "=r"(r[1]), "=r"(r[2]), "=r"(r[3]) : "r"(addr));
}
__device__ __forceinline__ void mma_f16(float c[4], const uint32_t a[4],
                                        uint32_t b0, uint32_t b1) {
    asm volatile("mma.sync.aligned.m16n8k16.row.col.f32.f16.f16.f32 "
        "{%0,%1,%2,%3}, {%4,%5,%6,%7}, {%8,%9}, {%0,%1,%2,%3};"
        : "+f"(c[0]), "+f"(c[1]), "+f"(c[2]), "+f"(c[3])
        : "r"(a[0]), "r"(a[1]), "r"(a[2]), "r"(a[3]), "r"(b0), "r"(b1));
}
__device__ __forceinline__ float silu_f(float v) { return v / (1.0f + __expf(-v)); }

// swizzled byte offset within a [rows][32 cols f16] tile (64B rows)
__device__ __forceinline__ uint32_t sw_off(int row, int c16) {
    return (uint32_t)(row * 64 + ((c16 ^ ((row >> 1) & 3)) << 4));
}

// ---------------- round: fp32 -> fp16 for x, w1 (w2 rides inside gemm<0>) ---
#define NX8  (M_ROWS * D_HID / 8)
#define NW18 (D_HID * D_HID / 8)
#define NW28 (KW * D_HID / 8)

__device__ __forceinline__ uint32_t pack2h(float a, float b) {
    __half2 h = __halves2half2(__float2half_rn(a), __float2half_rn(b));
    return *(uint32_t*)&h;
}
__device__ __forceinline__ void cvt8(const float* __restrict__ src,
                                     __half* __restrict__ dst, size_t j) {
    float4 v0 = ((const float4*)src)[2 * j];
    float4 v1 = ((const float4*)src)[2 * j + 1];
    uint4 o;
    o.x = pack2h(v0.x, v0.y); o.y = pack2h(v0.z, v0.w);
    o.z = pack2h(v1.x, v1.y); o.w = pack2h(v1.z, v1.w);
    ((uint4*)dst)[j] = o;
}

__global__ void round2_kernel(const float* __restrict__ x,
                              const float* __restrict__ w1,
                              __half* __restrict__ xh,
                              __half* __restrict__ w1h) {
    int i = blockIdx.x * blockDim.x + threadIdx.x;
    if (i < NX8)             cvt8(x, xh, i);
    else if (i < NX8 + NW18) cvt8(w1, w1h, i - NX8);
}

// ---------------- main mma.sync GEMM (1-pass FP16, CTA 128x128, warp 64x32) -
// stage: A_t0[128][32] @0, A_t1 @8192, B_t0 @16384, B_t1 @24576 (32 KB/stage)
#define STAGE_B 32768u
#define SMEM_BYTES (3 * 32768)   // 98304; epilogue reuses this region

template<int MODE>
__global__ void __launch_bounds__(256, 2)
gemm1p_kernel(const float* __restrict__ xin, const float* __restrict__ b2,
              float* __restrict__ out,
              const float* __restrict__ w2src, __half* __restrict__ w2dst) {
    extern __shared__ char smem[];
    uint32_t sb = smem_u32(smem);
    const int tid = threadIdx.x;
    const int l   = tid & 31;
    const int wid = tid >> 5;
    const int wm  = wid & 1;    // 2 M-warps (64 rows each)
    const int wn  = wid >> 1;   // 4 N-warps (32 cols each)
    const int bm = blockIdx.y * 128, bn = blockIdx.x * 128;

    const __half* Ah = (MODE == 0 ? g_xh : g_hh) + (size_t)bm * D_HID;
    const __half* Bh = (MODE == 0 ? g_w1h : g_w2h) + (size_t)bn * D_HID;

    // ---- hoisted cp.async addressing ----
    const int lrow = tid >> 2, lc16 = tid & 3;   // lrow 0..63
    const uint32_t so = sw_off(lrow, lc16);      // row+64 slot = +4096
    const __half* srcA = Ah + (size_t)lrow * D_HID + lc16 * 8;
    const __half* srcB = Bh + (size_t)lrow * D_HID + lc16 * 8;
    const size_t R64 = (size_t)64 * D_HID;

    // ---- hoisted ldmatrix offsets (tile-relative) ----
    uint32_t offA[4][2], offB[2][2];
    #pragma unroll
    for (int mt = 0; mt < 4; mt++) {
        int row = wm * 64 + mt * 16 + (l & 15);
        #pragma unroll
        for (int ks = 0; ks < 2; ks++)
            offA[mt][ks] = sw_off(row, ks * 2 + (l >> 4));
    }
    #pragma unroll
    for (int blk = 0; blk < 2; blk++) {
        int row = wn * 32 + blk * 16 + (l & 15);
        #pragma unroll
        for (int ks = 0; ks < 2; ks++)
            offB[blk][ks] = sw_off(row, ks * 2 + (l >> 4));
    }

    float acc[4][4][4];
    #pragma unroll
    for (int a = 0; a < 4; a++)
        #pragma unroll
        for (int b = 0; b < 4; b++)
            #pragma unroll
            for (int c = 0; c < 4; c++) acc[a][b][c] = 0.f;

    uint32_t sb0 = sb, sb1 = sb + STAGE_B, sb2 = sb + 2 * STAGE_B;

    // prefetch quarters: 2 cp16 each
    #define LD_Q0(base) do { uint32_t _t = (base) + so; \
        cp16(_t,             srcA);       cp16(_t + 4096,          srcA + R64); } while (0)
    #define LD_Q1(base) do { uint32_t _t = (base) + so; \
        cp16(_t + 8192,      srcA + 32);  cp16(_t + 8192 + 4096,   srcA + R64 + 32); \
        srcA += 64; } while (0)
    #define LD_Q2(base) do { uint32_t _t = (base) + so; \
        cp16(_t + 16384,     srcB);       cp16(_t + 16384 + 4096,  srcB + R64); } while (0)
    #define LD_Q3(base) do { uint32_t _t = (base) + so; \
        cp16(_t + 24576,     srcB + 32);  cp16(_t + 24576 + 4096,  srcB + R64 + 32); \
        srcB += 64; } while (0)

    // per-k16-slice compute: B ldsm + first A ldsm, start mma on a0 while
    // a1-a3 ldsm are in flight, then the rest as one unbroken run
    #define DO_SLICE(abase, bbase, ks) do { \
        uint32_t b0[4], b1[4], a0[4], a1[4], a2[4], a3[4]; \
        ldsm4(b0, (bbase) + offB[0][ks]); \
        ldsm4(b1, (bbase) + offB[1][ks]); \
        ldsm4(a0, (abase) + offA[0][ks]); \
        mma_f16(acc[0][0], a0, b0[0], b0[2]); \
        ldsm4(a1, (abase) + offA[1][ks]); \
        mma_f16(acc[0][1], a0, b0[1], b0[3]); \
        ldsm4(a2, (abase) + offA[2][ks]); \
        mma_f16(acc[0][2], a0, b1[0], b1[2]); \
        ldsm4(a3, (abase) + offA[3][ks]); \
        mma_f16(acc[0][3], a0, b1[1], b1[3]); \
        mma_f16(acc[1][0], a1, b0[0], b0[2]); \
        mma_f16(acc[1][1], a1, b0[1], b0[3]); \
        mma_f16(acc[1][2], a1, b1[0], b1[2]); \
        mma_f16(acc[1][3], a1, b1[1], b1[3]); \
        mma_f16(acc[2][0], a2, b0[0], b0[2]); \
        mma_f16(acc[2][1], a2, b0[1], b0[3]); \
        mma_f16(acc[2][2], a2, b1[0], b1[2]); \
        mma_f16(acc[2][3], a2, b1[1], b1[3]); \
        mma_f16(acc[3][0], a3, b0[0], b0[2]); \
        mma_f16(acc[3][1], a3, b0[1], b0[3]); \
        mma_f16(acc[3][2], a3, b1[0], b1[2]); \
        mma_f16(acc[3][3], a3, b1[1], b1[3]); \
    } while (0)

    LD_Q0(sb0); LD_Q1(sb0); LD_Q2(sb0); LD_Q3(sb0); CP_COMMIT();
    LD_Q0(sb1); LD_Q1(sb1); LD_Q2(sb1); LD_Q3(sb1); CP_COMMIT();

    const int NIT = D_HID / 64;   // 32
    for (int it = 0; it < NIT; it++) {
        CP_WAIT1();
        __syncthreads();
        const bool pf = (it < NIT - 2);
        // quarter-split prefetch: each 2-op LSU burst hides inside a 16-mma run
        if (pf) LD_Q0(sb2);
        DO_SLICE(sb0, sb0 + 16384u, 0);
        if (pf) LD_Q1(sb2);
        DO_SLICE(sb0, sb0 + 16384u, 1);
        if (pf) LD_Q2(sb2);
        DO_SLICE(sb0 + 8192u, sb0 + 24576u, 0);
        if (pf) LD_Q3(sb2);
        CP_COMMIT();
        DO_SLICE(sb0 + 8192u, sb0 + 24576u, 1);
        uint32_t t = sb0; sb0 = sb1; sb1 = sb2; sb2 = t;
    }
    __syncthreads();   // pipeline smem now reusable for epilogue

    if (MODE == 0) {
        // silu + round to fp16, staged for coalesced global stores
        uint32_t* h_buf = (uint32_t*)smem;            // [128][66]
        #pragma unroll
        for (int mt = 0; mt < 4; mt++) {
            #pragma unroll
            for (int nt = 0; nt < 4; nt++) {
                int r0 = wm * 64 + mt * 16 + (l >> 2);
                int cu = wn * 16 + nt * 4 + (l & 3);
                #pragma unroll
                for (int half = 0; half < 2; half++) {
                    int r = r0 + half * 8;
                    float v0 = silu_f(acc[mt][nt][half * 2 + 0]);
                    float v1 = silu_f(acc[mt][nt][half * 2 + 1]);
                    __half2 hp = __halves2half2(__float2half_rn(v0),
                                                __float2half_rn(v1));
                    h_buf[r * 66 + cu] = *(uint32_t*)&hp;
                }
            }
        }
        __syncthreads();
        for (int idx = tid; idx < 128 * 64; idx += 256) {
            int r = idx >> 6, c = idx & 63;
            ((uint32_t*)(g_hh + (size_t)(bm + r) * D_HID + bn))[c] = h_buf[r * 66 + c];
        }
        // ---- piggy-backed w2 fp32->fp16 conversion (consumed by gemm<1>) ----
        // 1024 CTAs x 2048 chunks x 8 elems = all of w2; DRAM pipe is ~97%
        // idle in this kernel, so this traffic rides nearly free.
        {
            int cta = blockIdx.y * gridDim.x + blockIdx.x;   // 0..1023
            size_t base = (size_t)cta * 2048 + tid;
            #pragma unroll
            for (int k = 0; k < 8; k++)
                cvt8(w2src, w2dst, base + (size_t)k * 256);
        }
    } else {
        // bias + causal 4-tap dynamic conv + silu, taps combined in-register:
        // lane l owns cols (l&3)*2,+1 of its 8-col group = taps {0,1} or {2,3}
        // of channel ch; pair (l, l^1) holds all 4 taps -> one shfl_xor(1).
        float* xs  = (float*)smem;                   // [131][33] = 17292 B
        float* ost = (float*)(smem + 17312);         // [128][33] = 16896 B
        float* b2s = (float*)(smem + 17312 + 16928); // [128]
        const int b  = bm >> 12;
        const int t0 = bm & (T_LEN - 1);
        const int d0 = bn >> 2;
        for (int idx = tid; idx < 131 * 32; idx += 256) {
            int r = idx >> 5, c = idx & 31;
            int t = t0 - 3 + r;
            float v = 0.f;
            if (t >= 0) v = xin[((size_t)b * T_LEN + t) * D_HID + d0 + c];
            xs[r * 33 + c] = v;
        }
        if (tid < 128) b2s[tid] = b2[bn + tid];
        __syncthreads();
        {
            const int ch = wn * 8 + ((l & 3) >> 1);  // + nt*2 below
            const int w0 = (l & 1) * 2;              // this lane's first tap
            #pragma unroll
            for (int mt = 0; mt < 4; mt++) {
                #pragma unroll
                for (int nt = 0; nt < 4; nt++) {
                    int colbase = wn * 32 + nt * 8 + (l & 3) * 2;
                    int chn = ch + nt * 2;
                    float k0 = b2s[colbase], k1 = b2s[colbase + 1];
                    #pragma unroll
                    for (int h = 0; h < 2; h++) {
                        int rr = wm * 64 + mt * 16 + (l >> 2) + h * 8;
                        float p = xs[(rr + w0) * 33 + chn] * (acc[mt][nt][h * 2] + k0)
                                + xs[(rr + w0 + 1) * 33 + chn] * (acc[mt][nt][h * 2 + 1] + k1);
                        p += __shfl_xor_sync(0xffffffffu, p, 1);
                        if ((l & 1) == 0) ost[rr * 33 + chn] = silu_f(p);
                    }
                }
            }
        }
        __syncthreads();
        for (int idx = tid; idx < 128 * 32; idx += 256) {
            int r = idx >> 5, c = idx & 31;
            out[(size_t)(bm + r) * D_HID + d0 + c] = ost[r * 33 + c];
        }
    }
}

// ---------------- launch ----------------------------------------------------
extern "C" void kernel_launch(void* const* d_in, const int* in_sizes, int n_in,
                              void* d_out, int out_size) {
    const float* x  = (const float*)d_in[0];   // [2,4096,2048]
    const float* w1 = (const float*)d_in[1];   // [2048,2048]
    const float* w2 = (const float*)d_in[2];   // [8192,2048]
    const float* b2 = (const float*)d_in[3];   // [8192]
    float* out = (float*)d_out;

    cudaFuncSetAttribute(gemm1p_kernel<0>, cudaFuncAttributeMaxDynamicSharedMemorySize, SMEM_BYTES);
    cudaFuncSetAttribute(gemm1p_kernel<1>, cudaFuncAttributeMaxDynamicSharedMemorySize, SMEM_BYTES);

    void *pxh, *pw1, *pw2;
    cudaGetSymbolAddress(&pxh, g_xh);
    cudaGetSymbolAddress(&pw1, g_w1h);
    cudaGetSymbolAddress(&pw2, g_w2h);

    {
        int ntot = NX8 + NW18;
        round2_kernel<<<(ntot + 255) / 256, 256>>>(x, w1, (__half*)pxh, (__half*)pw1);
    }

    dim3 g1(D_HID / 128, M_ROWS / 128);   // (16, 64) = 1024 CTAs
    gemm1p_kernel<0><<<g1, 256, SMEM_BYTES>>>(x, b2, out, w2, (__half*)pw2);

    dim3 g2(KW / 128, M_ROWS / 128);      // (64, 64)
    gemm1p_kernel<1><<<g2, 256, SMEM_BYTES>>>(x, b2, out, nullptr, nullptr);
}

// round 16
// speedup vs baseline: 1.0066x; 1.0066x over previous
#include <cuda_runtime.h>
#include <cuda_fp16.h>
#include <cstdint>
#include <cstddef>

#define D_HID 2048
#define T_LEN 4096
#define M_ROWS 8192
#define KW 8192

// ---------------- scratch (static device arrays: allocation-guard safe) ----
__device__ __align__(256) __half g_xh[(size_t)M_ROWS * D_HID];
__device__ __align__(256) __half g_w1h[(size_t)D_HID * D_HID];
__device__ __align__(256) __half g_w2h[(size_t)KW * D_HID];
__device__ __align__(256) __half g_hh[(size_t)M_ROWS * D_HID];

// ---------------- helpers ---------------------------------------------------
__device__ __forceinline__ uint32_t smem_u32(const void* p) {
    uint32_t a;
    asm("{ .reg .u64 t; cvta.to.shared.u64 t, %1; cvt.u32.u64 %0, t; }"
        : "=r"(a) : "l"(p));
    return a;
}
__device__ __forceinline__ void cp16(uint32_t dst, const void* src) {
    asm volatile("cp.async.cg.shared.global [%0], [%1], 16;" :: "r"(dst), "l"(src));
}
#define CP_COMMIT() asm volatile("cp.async.commit_group;" ::: "memory")
#define CP_WAIT1()  asm volatile("cp.async.wait_group 1;" ::: "memory")

__device__ __forceinline__ void ldsm4(uint32_t r[4], uint32_t addr) {
    asm volatile("ldmatrix.sync.aligned.m8n8.x4.shared.b16 {%0,%1,%2,%3}, [%4];"
        : "=r"(r[0]), "=r"(r[1]), "=r"(r[2]), "=r"(r[3]) : "r"(addr));
}
__device__ __forceinline__ void mma_f16(float c[4], const uint32_t a[4],
                                        uint32_t b0, uint32_t b1) {
    asm volatile("mma.sync.aligned.m16n8k16.row.col.f32.f16.f16.f32 "
        "{%0,%1,%2,%3}, {%4,%5,%6,%7}, {%8,%9}, {%0,%1,%2,%3};"
        : "+f"(c[0]), "+f"(c[1]), "+f"(c[2]), "+f"(c[3])
        : "r"(a[0]), "r"(a[1]), "r"(a[2]), "r"(a[3]), "r"(b0), "r"(b1));
}
__device__ __forceinline__ float silu_f(float v) { return v / (1.0f + __expf(-v)); }

// swizzled byte offset within a [rows][32 cols f16] tile (64B rows)
__device__ __forceinline__ uint32_t sw_off(int row, int c16) {
    return (uint32_t)(row * 64 + ((c16 ^ ((row >> 1) & 3)) << 4));
}

// ---------------- round: fp32 -> fp16 for x, w1 (w2 rides inside gemm<0>) ---
#define NX8  (M_ROWS * D_HID / 8)
#define NW18 (D_HID * D_HID / 8)

__device__ __forceinline__ uint32_t pack2h(float a, float b) {
    __half2 h = __halves2half2(__float2half_rn(a), __float2half_rn(b));
    return *(uint32_t*)&h;
}
__device__ __forceinline__ void cvt8(const float* __restrict__ src,
                                     __half* __restrict__ dst, size_t j) {
    float4 v0 = ((const float4*)src)[2 * j];
    float4 v1 = ((const float4*)src)[2 * j + 1];
    uint4 o;
    o.x = pack2h(v0.x, v0.y); o.y = pack2h(v0.z, v0.w);
    o.z = pack2h(v1.x, v1.y); o.w = pack2h(v1.z, v1.w);
    ((uint4*)dst)[j] = o;
}

__global__ void round2_kernel(const float* __restrict__ x,
                              const float* __restrict__ w1,
                              __half* __restrict__ xh,
                              __half* __restrict__ w1h) {
    int i = blockIdx.x * blockDim.x + threadIdx.x;
    if (i < NX8)             cvt8(x, xh, i);
    else if (i < NX8 + NW18) cvt8(w1, w1h, i - NX8);
}

// ---------------- main mma.sync GEMM (1-pass FP16, CTA 128x128, warp 64x32) -
// stage: A_t0[128][32] @0, A_t1 @8192, B_t0 @16384, B_t1 @24576 (32 KB/stage)
#define STAGE_B 32768u
#define SMEM_BYTES (3 * 32768)   // 98304; epilogue reuses this region

template<int MODE>
__global__ void __launch_bounds__(256, 2)
gemm1p_kernel(const float* __restrict__ xin, const float* __restrict__ b2,
              float* __restrict__ out,
              const float* __restrict__ w2src, __half* __restrict__ w2dst) {
    extern __shared__ char smem[];
    uint32_t sb = smem_u32(smem);
    const int tid = threadIdx.x;
    const int l   = tid & 31;
    const int wid = tid >> 5;
    const int wm  = wid & 1;    // 2 M-warps (64 rows each)
    const int wn  = wid >> 1;   // 4 N-warps (32 cols each)
    const int bm = blockIdx.y * 128, bn = blockIdx.x * 128;

    const __half* Ah = (MODE == 0 ? g_xh : g_hh) + (size_t)bm * D_HID;
    const __half* Bh = (MODE == 0 ? g_w1h : g_w2h) + (size_t)bn * D_HID;

    // ---- hoisted cp.async addressing ----
    const int lrow = tid >> 2, lc16 = tid & 3;   // lrow 0..63
    const uint32_t so = sw_off(lrow, lc16);      // row+64 slot = +4096
    const __half* srcA = Ah + (size_t)lrow * D_HID + lc16 * 8;
    const __half* srcB = Bh + (size_t)lrow * D_HID + lc16 * 8;
    const size_t R64 = (size_t)64 * D_HID;

    // ---- hoisted ldmatrix offsets (tile-relative) ----
    uint32_t offA[4][2], offB[2][2];
    #pragma unroll
    for (int mt = 0; mt < 4; mt++) {
        int row = wm * 64 + mt * 16 + (l & 15);
        #pragma unroll
        for (int ks = 0; ks < 2; ks++)
            offA[mt][ks] = sw_off(row, ks * 2 + (l >> 4));
    }
    #pragma unroll
    for (int blk = 0; blk < 2; blk++) {
        int row = wn * 32 + blk * 16 + (l & 15);
        #pragma unroll
        for (int ks = 0; ks < 2; ks++)
            offB[blk][ks] = sw_off(row, ks * 2 + (l >> 4));
    }

    float acc[4][4][4];
    #pragma unroll
    for (int a = 0; a < 4; a++)
        #pragma unroll
        for (int b = 0; b < 4; b++)
            #pragma unroll
            for (int c = 0; c < 4; c++) acc[a][b][c] = 0.f;

    uint32_t sb0 = sb, sb1 = sb + STAGE_B, sb2 = sb + 2 * STAGE_B;

    // prefetch quarters: 2 cp16 each
    #define LD_Q0(base) do { uint32_t _t = (base) + so; \
        cp16(_t,             srcA);       cp16(_t + 4096,          srcA + R64); } while (0)
    #define LD_Q1(base) do { uint32_t _t = (base) + so; \
        cp16(_t + 8192,      srcA + 32);  cp16(_t + 8192 + 4096,   srcA + R64 + 32); \
        srcA += 64; } while (0)
    #define LD_Q2(base) do { uint32_t _t = (base) + so; \
        cp16(_t + 16384,     srcB);       cp16(_t + 16384 + 4096,  srcB + R64); } while (0)
    #define LD_Q3(base) do { uint32_t _t = (base) + so; \
        cp16(_t + 24576,     srcB + 32);  cp16(_t + 24576 + 4096,  srcB + R64 + 32); \
        srcB += 64; } while (0)

    // per-k16-slice compute: B ldsm + first A ldsm, start mma on a0 while
    // a1-a3 ldsm are in flight, then the rest as one unbroken run
    #define DO_SLICE(abase, bbase, ks) do { \
        uint32_t b0[4], b1[4], a0[4], a1[4], a2[4], a3[4]; \
        ldsm4(b0, (bbase) + offB[0][ks]); \
        ldsm4(b1, (bbase) + offB[1][ks]); \
        ldsm4(a0, (abase) + offA[0][ks]); \
        mma_f16(acc[0][0], a0, b0[0], b0[2]); \
        ldsm4(a1, (abase) + offA[1][ks]); \
        mma_f16(acc[0][1], a0, b0[1], b0[3]); \
        ldsm4(a2, (abase) + offA[2][ks]); \
        mma_f16(acc[0][2], a0, b1[0], b1[2]); \
        ldsm4(a3, (abase) + offA[3][ks]); \
        mma_f16(acc[0][3], a0, b1[1], b1[3]); \
        mma_f16(acc[1][0], a1, b0[0], b0[2]); \
        mma_f16(acc[1][1], a1, b0[1], b0[3]); \
        mma_f16(acc[1][2], a1, b1[0], b1[2]); \
        mma_f16(acc[1][3], a1, b1[1], b1[3]); \
        mma_f16(acc[2][0], a2, b0[0], b0[2]); \
        mma_f16(acc[2][1], a2, b0[1], b0[3]); \
        mma_f16(acc[2][2], a2, b1[0], b1[2]); \
        mma_f16(acc[2][3], a2, b1[1], b1[3]); \
        mma_f16(acc[3][0], a3, b0[0], b0[2]); \
        mma_f16(acc[3][1], a3, b0[1], b0[3]); \
        mma_f16(acc[3][2], a3, b1[0], b1[2]); \
        mma_f16(acc[3][3], a3, b1[1], b1[3]); \
    } while (0)

    // ---- w2 fp32->fp16 conversion, software-pipelined through the mainloop
    // (MODE 0 only). 1 float4 load + 1 uint2 store per iteration for
    // iterations 0..15; data loaded a full iteration earlier, so the DRAM
    // scoreboard is long drained by store time. No tail exposure.
    const float4* w2f4 = (const float4*)w2src;
    uint2* w2u2 = (uint2*)w2dst;
    size_t cvj = 0;
    float4 pv = {0.f, 0.f, 0.f, 0.f};
    if (MODE == 0) {
        cvj = (size_t)(blockIdx.y * gridDim.x + blockIdx.x) * 4096 + tid;
        pv = w2f4[cvj];
    }

    LD_Q0(sb0); LD_Q1(sb0); LD_Q2(sb0); LD_Q3(sb0); CP_COMMIT();
    LD_Q0(sb1); LD_Q1(sb1); LD_Q2(sb1); LD_Q3(sb1); CP_COMMIT();

    const int NIT = D_HID / 64;   // 32
    for (int it = 0; it < NIT; it++) {
        CP_WAIT1();
        __syncthreads();
        if (MODE == 0 && it < 16) {
            uint2 o;
            o.x = pack2h(pv.x, pv.y);
            o.y = pack2h(pv.z, pv.w);
            w2u2[cvj] = o;
            if (it < 15) { cvj += 256; pv = w2f4[cvj]; }
        }
        const bool pf = (it < NIT - 2);
        // quarter-split prefetch: each 2-op LSU burst hides inside a 16-mma run
        if (pf) LD_Q0(sb2);
        DO_SLICE(sb0, sb0 + 16384u, 0);
        if (pf) LD_Q1(sb2);
        DO_SLICE(sb0, sb0 + 16384u, 1);
        if (pf) LD_Q2(sb2);
        DO_SLICE(sb0 + 8192u, sb0 + 24576u, 0);
        if (pf) LD_Q3(sb2);
        CP_COMMIT();
        DO_SLICE(sb0 + 8192u, sb0 + 24576u, 1);
        uint32_t t = sb0; sb0 = sb1; sb1 = sb2; sb2 = t;
    }
    __syncthreads();   // pipeline smem now reusable for epilogue

    if (MODE == 0) {
        // silu + round to fp16, staged for coalesced global stores
        uint32_t* h_buf = (uint32_t*)smem;            // [128][66]
        #pragma unroll
        for (int mt = 0; mt < 4; mt++) {
            #pragma unroll
            for (int nt = 0; nt < 4; nt++) {
                int r0 = wm * 64 + mt * 16 + (l >> 2);
                int cu = wn * 16 + nt * 4 + (l & 3);
                #pragma unroll
                for (int half = 0; half < 2; half++) {
                    int r = r0 + half * 8;
                    float v0 = silu_f(acc[mt][nt][half * 2 + 0]);
                    float v1 = silu_f(acc[mt][nt][half * 2 + 1]);
                    __half2 hp = __halves2half2(__float2half_rn(v0),
                                                __float2half_rn(v1));
                    h_buf[r * 66 + cu] = *(uint32_t*)&hp;
                }
            }
        }
        __syncthreads();
        for (int idx = tid; idx < 128 * 64; idx += 256) {
            int r = idx >> 6, c = idx & 63;
            ((uint32_t*)(g_hh + (size_t)(bm + r) * D_HID + bn))[c] = h_buf[r * 66 + c];
        }
    } else {
        // bias + causal 4-tap dynamic conv + silu, taps combined in-register:
        // lane l owns cols (l&3)*2,+1 of its 8-col group = taps {0,1} or {2,3}
        // of channel ch; pair (l, l^1) holds all 4 taps -> one shfl_xor(1).
        float* xs  = (float*)smem;                   // [131][33] = 17292 B
        float* ost = (float*)(smem + 17312);         // [128][33] = 16896 B
        float* b2s = (float*)(smem + 17312 + 16928); // [128]
        const int b  = bm >> 12;
        const int t0 = bm & (T_LEN - 1);
        const int d0 = bn >> 2;
        for (int idx = tid; idx < 131 * 32; idx += 256) {
            int r = idx >> 5, c = idx & 31;
            int t = t0 - 3 + r;
            float v = 0.f;
            if (t >= 0) v = xin[((size_t)b * T_LEN + t) * D_HID + d0 + c];
            xs[r * 33 + c] = v;
        }
        if (tid < 128) b2s[tid] = b2[bn + tid];
        __syncthreads();
        {
            const int ch = wn * 8 + ((l & 3) >> 1);  // + nt*2 below
            const int w0 = (l & 1) * 2;              // this lane's first tap
            #pragma unroll
            for (int mt = 0; mt < 4; mt++) {
                #pragma unroll
                for (int nt = 0; nt < 4; nt++) {
                    int colbase = wn * 32 + nt * 8 + (l & 3) * 2;
                    int chn = ch + nt * 2;
                    float k0 = b2s[colbase], k1 = b2s[colbase + 1];
                    #pragma unroll
                    for (int h = 0; h < 2; h++) {
                        int rr = wm * 64 + mt * 16 + (l >> 2) + h * 8;
                        float p = xs[(rr + w0) * 33 + chn] * (acc[mt][nt][h * 2] + k0)
                                + xs[(rr + w0 + 1) * 33 + chn] * (acc[mt][nt][h * 2 + 1] + k1);
                        p += __shfl_xor_sync(0xffffffffu, p, 1);
                        if ((l & 1) == 0) ost[rr * 33 + chn] = silu_f(p);
                    }
                }
            }
        }
        __syncthreads();
        for (int idx = tid; idx < 128 * 32; idx += 256) {
            int r = idx >> 5, c = idx & 31;
            out[(size_t)(bm + r) * D_HID + d0 + c] = ost[r * 33 + c];
        }
    }
}

// ---------------- launch ----------------------------------------------------
extern "C" void kernel_launch(void* const* d_in, const int* in_sizes, int n_in,
                              void* d_out, int out_size) {
    const float* x  = (const float*)d_in[0];   // [2,4096,2048]
    const float* w1 = (const float*)d_in[1];   // [2048,2048]
    const float* w2 = (const float*)d_in[2];   // [8192,2048]
    const float* b2 = (const float*)d_in[3];   // [8192]
    float* out = (float*)d_out;

    cudaFuncSetAttribute(gemm1p_kernel<0>, cudaFuncAttributeMaxDynamicSharedMemorySize, SMEM_BYTES);
    cudaFuncSetAttribute(gemm1p_kernel<1>, cudaFuncAttributeMaxDynamicSharedMemorySize, SMEM_BYTES);

    void *pxh, *pw1, *pw2;
    cudaGetSymbolAddress(&pxh, g_xh);
    cudaGetSymbolAddress(&pw1, g_w1h);
    cudaGetSymbolAddress(&pw2, g_w2h);

    {
        int ntot = NX8 + NW18;
        round2_kernel<<<(ntot + 255) / 256, 256>>>(x, w1, (__half*)pxh, (__half*)pw1);
    }

    dim3 g1(D_HID / 128, M_ROWS / 128);   // (16, 64) = 1024 CTAs
    gemm1p_kernel<0><<<g1, 256, SMEM_BYTES>>>(x, b2, out, w2, (__half*)pw2);

    dim3 g2(KW / 128, M_ROWS / 128);      // (64, 64)
    gemm1p_kernel<1><<<g2, 256, SMEM_BYTES>>>(x, b2, out, nullptr, nullptr);
}